// round 11
// baseline (speedup 1.0000x reference)
#include <cuda_runtime.h>
#include <math.h>

#define NN 8192
#define FF 64
#define SLOPEC 3.0f

// ---------------- scratch (device globals; no allocations allowed) -------------
__device__ float g_xe[NN * FF];                      // encoded features (2 MB)
__device__ float g_S[(size_t)NN * NN];               // logits S = xe xe^T (256 MB)
__device__ float g_dpart[32 * NN];                   // partial column sums of exp(S)
__device__ float g_invD[NN];                         // 1 / column sum
__device__ float g_outpart[8 * NN * FF];             // K-split partials of attn@xe (16 MB)
__device__ float g_colsum_part[32 * FF];
__device__ float g_sumsq_part[32];

// ---------------- K1: per-element encoder MLP 2->4->4->1 (tanh each) ----------
__global__ void k_encode(const float* __restrict__ x,
                         const float* __restrict__ w1, const float* __restrict__ b1,
                         const float* __restrict__ w2, const float* __restrict__ b2,
                         const float* __restrict__ w3, const float* __restrict__ b3) {
    int idx = blockIdx.x * 256 + threadIdx.x;        // < NN*FF
    float2 xv = ((const float2*)x)[idx];
    float h1[4], h2[4];
#pragma unroll
    for (int j = 0; j < 4; j++)
        h1[j] = tanhf(xv.x * __ldg(w1 + j) + xv.y * __ldg(w1 + 4 + j) + __ldg(b1 + j));
#pragma unroll
    for (int j = 0; j < 4; j++)
        h2[j] = tanhf(h1[0] * __ldg(w2 + j) + h1[1] * __ldg(w2 + 4 + j) +
                      h1[2] * __ldg(w2 + 8 + j) + h1[3] * __ldg(w2 + 12 + j) + __ldg(b2 + j));
    float o = tanhf(h2[0] * __ldg(w3 + 0) + h2[1] * __ldg(w3 + 1) +
                    h2[2] * __ldg(w3 + 2) + h2[3] * __ldg(w3 + 3) + __ldg(b3));
    g_xe[idx] = o;
}

// ---------------- K2: S = xe * xe^T  (fp32, 128x128 tile, K=64) ---------------
#define SPAD 132   // padded tile row length; 132*4 bytes is 16B-aligned, reduces STS conflicts
__global__ __launch_bounds__(256, 2) void k_gemm_s() {
    __shared__ float sa[32][SPAD];   // [k][m] transposed A tile (i rows)
    __shared__ float sb[32][SPAD];   // [k][n] transposed A tile (j rows)
    const int i0 = blockIdx.y * 128;
    const int j0 = blockIdx.x * 128;
    const int t  = threadIdx.x;
    const int tx = t & 15, ty = t >> 4;
    const int kf4 = t & 7, rr = t >> 3;     // load mapping: 8 f4 per k-row, 32 row groups

    float acc[2][2][4][4];
#pragma unroll
    for (int a = 0; a < 2; a++)
#pragma unroll
        for (int b = 0; b < 2; b++)
#pragma unroll
            for (int r = 0; r < 4; r++)
#pragma unroll
                for (int c = 0; c < 4; c++) acc[a][b][r][c] = 0.f;

    for (int kb = 0; kb < 64; kb += 32) {
        __syncthreads();
#pragma unroll
        for (int l = 0; l < 4; l++) {
            int row = rr + l * 32;
            float4 va = *(const float4*)(g_xe + (size_t)(i0 + row) * FF + kb + kf4 * 4);
            sa[kf4 * 4 + 0][row] = va.x; sa[kf4 * 4 + 1][row] = va.y;
            sa[kf4 * 4 + 2][row] = va.z; sa[kf4 * 4 + 3][row] = va.w;
            float4 vb = *(const float4*)(g_xe + (size_t)(j0 + row) * FF + kb + kf4 * 4);
            sb[kf4 * 4 + 0][row] = vb.x; sb[kf4 * 4 + 1][row] = vb.y;
            sb[kf4 * 4 + 2][row] = vb.z; sb[kf4 * 4 + 3][row] = vb.w;
        }
        __syncthreads();
#pragma unroll 4
        for (int k = 0; k < 32; k++) {
            float a0[4], a1[4], b0[4], b1[4];
            *(float4*)a0 = *(const float4*)&sa[k][ty * 4];
            *(float4*)a1 = *(const float4*)&sa[k][64 + ty * 4];
            *(float4*)b0 = *(const float4*)&sb[k][tx * 4];
            *(float4*)b1 = *(const float4*)&sb[k][64 + tx * 4];
#pragma unroll
            for (int r = 0; r < 4; r++)
#pragma unroll
                for (int c = 0; c < 4; c++) {
                    acc[0][0][r][c] += a0[r] * b0[c];
                    acc[0][1][r][c] += a0[r] * b1[c];
                    acc[1][0][r][c] += a1[r] * b0[c];
                    acc[1][1][r][c] += a1[r] * b1[c];
                }
        }
    }
#pragma unroll
    for (int a = 0; a < 2; a++)
#pragma unroll
        for (int r = 0; r < 4; r++) {
            size_t i = (size_t)(i0 + a * 64 + ty * 4 + r);
            float4 v0 = make_float4(acc[a][0][r][0], acc[a][0][r][1], acc[a][0][r][2], acc[a][0][r][3]);
            float4 v1 = make_float4(acc[a][1][r][0], acc[a][1][r][1], acc[a][1][r][2], acc[a][1][r][3]);
            *(float4*)(g_S + i * NN + j0 + tx * 4)      = v0;
            *(float4*)(g_S + i * NN + j0 + 64 + tx * 4) = v1;
        }
}

// ---------------- K3: partial column sums of exp(S) ---------------------------
// |S| < 64 strictly (tanh outputs), so exp(S) and its sums stay in fp32 range;
// skipping max-subtraction is mathematically identical to the reference softmax.
__global__ void k_colsum() {
    int j  = blockIdx.x * 256 + threadIdx.x;
    int r0 = blockIdx.y * 256;
    const float* p = g_S + (size_t)r0 * NN + j;
    float d = 0.f;
    for (int r = 0; r < 256; r += 8) {
        float v[8];
#pragma unroll
        for (int u = 0; u < 8; u++) v[u] = p[(size_t)(r + u) * NN];
#pragma unroll
        for (int u = 0; u < 8; u++) d += __expf(v[u]);
    }
    g_dpart[blockIdx.y * NN + j] = d;
}

__global__ void k_invd() {
    int j = blockIdx.x * 256 + threadIdx.x;
    float d = 0.f;
#pragma unroll
    for (int s = 0; s < 32; s++) d += g_dpart[s * NN + j];
    g_invD[j] = 1.0f / d;
}

// ---------------- K4: out = exp(S) @ (xe * invD), K split into 8 slices -------
__global__ __launch_bounds__(256) void k_av() {
    __shared__ float Ps[32][SPAD];   // [j][i] exp(S) tile, transposed
    __shared__ float vs[32][72];     // [j][f] scaled value tile
    const int i0    = blockIdx.x * 128;
    const int jbase = blockIdx.y * 1024;
    const int t  = threadIdx.x;
    const int tx = t & 15, ty = t >> 4;
    const int jf4 = t & 7, rr = t >> 3;

    float acc[2][4][4];
#pragma unroll
    for (int a = 0; a < 2; a++)
#pragma unroll
        for (int r = 0; r < 4; r++)
#pragma unroll
            for (int c = 0; c < 4; c++) acc[a][r][c] = 0.f;

    for (int ch = 0; ch < 32; ch++) {
        int j0 = jbase + ch * 32;
        __syncthreads();
#pragma unroll
        for (int l = 0; l < 4; l++) {
            int row = rr + l * 32;
            float4 s = *(const float4*)(g_S + (size_t)(i0 + row) * NN + j0 + jf4 * 4);
            Ps[jf4 * 4 + 0][row] = __expf(s.x);
            Ps[jf4 * 4 + 1][row] = __expf(s.y);
            Ps[jf4 * 4 + 2][row] = __expf(s.z);
            Ps[jf4 * 4 + 3][row] = __expf(s.w);
        }
#pragma unroll
        for (int l = 0; l < 2; l++) {
            int q = t + l * 256;
            int jj = q >> 4, fp = q & 15;
            float inv = __ldg(g_invD + j0 + jj);
            float4 v = *(const float4*)(g_xe + (size_t)(j0 + jj) * FF + fp * 4);
            v.x *= inv; v.y *= inv; v.z *= inv; v.w *= inv;
            *(float4*)&vs[jj][fp * 4] = v;
        }
        __syncthreads();
#pragma unroll 4
        for (int jj = 0; jj < 32; jj++) {
            float p0[4], p1[4], vv[4];
            *(float4*)p0 = *(const float4*)&Ps[jj][ty * 4];
            *(float4*)p1 = *(const float4*)&Ps[jj][64 + ty * 4];
            *(float4*)vv = *(const float4*)&vs[jj][tx * 4];
#pragma unroll
            for (int r = 0; r < 4; r++)
#pragma unroll
                for (int c = 0; c < 4; c++) {
                    acc[0][r][c] += p0[r] * vv[c];
                    acc[1][r][c] += p1[r] * vv[c];
                }
        }
    }
    float* op = g_outpart + (size_t)blockIdx.y * NN * FF;
#pragma unroll
    for (int a = 0; a < 2; a++)
#pragma unroll
        for (int r = 0; r < 4; r++) {
            float4 v = make_float4(acc[a][r][0], acc[a][r][1], acc[a][r][2], acc[a][r][3]);
            *(float4*)(op + (size_t)(i0 + a * 64 + ty * 4 + r) * FF + tx * 4) = v;
        }
}

// ---------------- K4r: deterministic reduction of the 8 K-slices --------------
__global__ void k_reduce_out(float* __restrict__ out) {
    int q = blockIdx.x * 256 + threadIdx.x;      // float4 index < NN*FF/4
    float4 s = ((const float4*)g_outpart)[q];
#pragma unroll
    for (int p = 1; p < 8; p++) {
        float4 v = ((const float4*)(g_outpart + (size_t)p * NN * FF))[q];
        s.x += v.x; s.y += v.y; s.z += v.z; s.w += v.w;
    }
    ((float4*)out)[q] = s;
}

// ---------------- K5a: row sum-of-squares + column sums (partials) ------------
__global__ void k_stats(const float* __restrict__ out) {
    __shared__ float sh[256];
    int b = blockIdx.x, t = threadIdx.x;
    // phase A: per-row sum of squares
    const float4* row = (const float4*)(out + (size_t)(b * 256 + t) * FF);
    float ss = 0.f;
#pragma unroll
    for (int i = 0; i < 16; i++) {
        float4 v = row[i];
        ss += v.x * v.x + v.y * v.y + v.z * v.z + v.w * v.w;
    }
    sh[t] = ss;
    __syncthreads();
    for (int s = 128; s > 0; s >>= 1) {
        if (t < s) sh[t] += sh[t + s];
        __syncthreads();
    }
    if (t == 0) g_sumsq_part[b] = sh[0];
    __syncthreads();
    // phase B: column sums over this block's 256 rows
    int f = t & 63, g = t >> 6;
    float cs = 0.f;
    for (int r = 0; r < 64; r++) cs += out[(size_t)(b * 256 + g * 64 + r) * FF + f];
    sh[t] = cs;
    __syncthreads();
    if (t < 64) g_colsum_part[b * FF + t] = sh[t] + sh[t + 64] + sh[t + 128] + sh[t + 192];
}

// ---------------- K5b: final mean(E) + alpha/beta MLPs ------------------------
__global__ void k_final(float* __restrict__ out,
                        const float* __restrict__ wa1, const float* __restrict__ ba1,
                        const float* __restrict__ wa2, const float* __restrict__ ba2,
                        const float* __restrict__ wb1, const float* __restrict__ bb1,
                        const float* __restrict__ wb2, const float* __restrict__ bb2) {
    __shared__ float sh[64];
    int t = threadIdx.x;                 // 64 threads
    float cs = 0.f;
    for (int b = 0; b < 32; b++) cs += g_colsum_part[b * FF + t];
    sh[t] = cs * cs;
    __syncthreads();
    if (t == 0) {
        float s2 = 0.f;
        for (int i = 0; i < 64; i++) s2 += sh[i];
        float sq = 0.f;
        for (int b = 0; b < 32; b++) sq += g_sumsq_part[b];
        // mean(E) = 2*mean_i(sq_i) - (2/N^2) * sum_f colsum_f^2
        float m = 2.0f * sq / (float)NN - 2.0f * s2 / ((float)NN * (float)NN);
        // alpha MLP: 1->2->1, tanh after every linear
        float ha0 = tanhf(m * __ldg(wa1 + 0) + __ldg(ba1 + 0));
        float ha1 = tanhf(m * __ldg(wa1 + 1) + __ldg(ba1 + 1));
        float ao  = tanhf(ha0 * __ldg(wa2 + 0) + ha1 * __ldg(wa2 + 1) + __ldg(ba2));
        // beta MLP
        float hb0 = tanhf(m * __ldg(wb1 + 0) + __ldg(bb1 + 0));
        float hb1 = tanhf(m * __ldg(wb1 + 1) + __ldg(bb1 + 1));
        float bo  = tanhf(hb0 * __ldg(wb2 + 0) + hb1 * __ldg(wb2 + 1) + __ldg(bb2));
        out[NN * FF]     = expf(SLOPEC * ao);
        out[NN * FF + 1] = expf(-SLOPEC * bo);
    }
}

// ---------------- launch ------------------------------------------------------
extern "C" void kernel_launch(void* const* d_in, const int* in_sizes, int n_in,
                              void* d_out, int out_size) {
    const float* x     = (const float*)d_in[0];
    const float* w_in1 = (const float*)d_in[1];
    const float* b_in1 = (const float*)d_in[2];
    const float* w_in2 = (const float*)d_in[3];
    const float* b_in2 = (const float*)d_in[4];
    const float* w_in3 = (const float*)d_in[5];
    const float* b_in3 = (const float*)d_in[6];
    const float* w_a1  = (const float*)d_in[7];
    const float* b_a1  = (const float*)d_in[8];
    const float* w_a2  = (const float*)d_in[9];
    const float* b_a2  = (const float*)d_in[10];
    const float* w_b1  = (const float*)d_in[11];
    const float* b_b1  = (const float*)d_in[12];
    const float* w_b2  = (const float*)d_in[13];
    const float* b_b2  = (const float*)d_in[14];
    float* out = (float*)d_out;

    k_encode<<<NN * FF / 256, 256>>>(x, w_in1, b_in1, w_in2, b_in2, w_in3, b_in3);
    k_gemm_s<<<dim3(64, 64), 256>>>();
    k_colsum<<<dim3(32, 32), 256>>>();
    k_invd<<<32, 256>>>();
    k_av<<<dim3(64, 8), 256>>>();
    k_reduce_out<<<NN * FF / 4 / 256, 256>>>(out);
    k_stats<<<32, 256>>>(out);
    k_final<<<1, 64>>>(out, w_a1, b_a1, w_a2, b_a2, w_b1, b_b1, w_b2, b_b2);
}

// round 12
// speedup vs baseline: 1.0012x; 1.0012x over previous
#include <cuda_runtime.h>
#include <math.h>

#define NN 8192
#define FF 64
#define SLOPEC 3.0f

// ---------------- scratch (device globals; no allocations allowed) -------------
__device__ float g_xe[NN * FF];                      // encoded features (2 MB)
__device__ float g_S[(size_t)NN * NN];               // logits S = xe xe^T (256 MB)
__device__ float g_dpart[32 * NN];                   // partial column sums of exp(S)
__device__ float g_invD[NN];                         // 1 / column sum
__device__ float g_outpart[8 * NN * FF];             // K-split partials of attn@xe (16 MB)
__device__ float g_colsum_part[32 * FF];
__device__ float g_sumsq_part[32];

// ---------------- K1: per-element encoder MLP 2->4->4->1 (tanh each) ----------
__global__ void k_encode(const float* __restrict__ x,
                         const float* __restrict__ w1, const float* __restrict__ b1,
                         const float* __restrict__ w2, const float* __restrict__ b2,
                         const float* __restrict__ w3, const float* __restrict__ b3) {
    int idx = blockIdx.x * 256 + threadIdx.x;        // < NN*FF
    float2 xv = ((const float2*)x)[idx];
    float h1[4], h2[4];
#pragma unroll
    for (int j = 0; j < 4; j++)
        h1[j] = tanhf(xv.x * __ldg(w1 + j) + xv.y * __ldg(w1 + 4 + j) + __ldg(b1 + j));
#pragma unroll
    for (int j = 0; j < 4; j++)
        h2[j] = tanhf(h1[0] * __ldg(w2 + j) + h1[1] * __ldg(w2 + 4 + j) +
                      h1[2] * __ldg(w2 + 8 + j) + h1[3] * __ldg(w2 + 12 + j) + __ldg(b2 + j));
    float o = tanhf(h2[0] * __ldg(w3 + 0) + h2[1] * __ldg(w3 + 1) +
                    h2[2] * __ldg(w3 + 2) + h2[3] * __ldg(w3 + 3) + __ldg(b3));
    g_xe[idx] = o;
}

// ---------------- K2: S = xe * xe^T  (fp32, 128x128 tile, K=64) ---------------
#define SPAD 132   // padded tile row length; 132*4 bytes is 16B-aligned, reduces STS conflicts
__global__ __launch_bounds__(256, 2) void k_gemm_s() {
    __shared__ float sa[32][SPAD];   // [k][m] transposed A tile (i rows)
    __shared__ float sb[32][SPAD];   // [k][n] transposed A tile (j rows)
    const int i0 = blockIdx.y * 128;
    const int j0 = blockIdx.x * 128;
    const int t  = threadIdx.x;
    const int tx = t & 15, ty = t >> 4;
    const int kf4 = t & 7, rr = t >> 3;     // load mapping: 8 f4 per k-row, 32 row groups

    float acc[2][2][4][4];
#pragma unroll
    for (int a = 0; a < 2; a++)
#pragma unroll
        for (int b = 0; b < 2; b++)
#pragma unroll
            for (int r = 0; r < 4; r++)
#pragma unroll
                for (int c = 0; c < 4; c++) acc[a][b][r][c] = 0.f;

    for (int kb = 0; kb < 64; kb += 32) {
        __syncthreads();
#pragma unroll
        for (int l = 0; l < 4; l++) {
            int row = rr + l * 32;
            float4 va = *(const float4*)(g_xe + (size_t)(i0 + row) * FF + kb + kf4 * 4);
            sa[kf4 * 4 + 0][row] = va.x; sa[kf4 * 4 + 1][row] = va.y;
            sa[kf4 * 4 + 2][row] = va.z; sa[kf4 * 4 + 3][row] = va.w;
            float4 vb = *(const float4*)(g_xe + (size_t)(j0 + row) * FF + kb + kf4 * 4);
            sb[kf4 * 4 + 0][row] = vb.x; sb[kf4 * 4 + 1][row] = vb.y;
            sb[kf4 * 4 + 2][row] = vb.z; sb[kf4 * 4 + 3][row] = vb.w;
        }
        __syncthreads();
#pragma unroll 4
        for (int k = 0; k < 32; k++) {
            float a0[4], a1[4], b0[4], b1[4];
            *(float4*)a0 = *(const float4*)&sa[k][ty * 4];
            *(float4*)a1 = *(const float4*)&sa[k][64 + ty * 4];
            *(float4*)b0 = *(const float4*)&sb[k][tx * 4];
            *(float4*)b1 = *(const float4*)&sb[k][64 + tx * 4];
#pragma unroll
            for (int r = 0; r < 4; r++)
#pragma unroll
                for (int c = 0; c < 4; c++) {
                    acc[0][0][r][c] += a0[r] * b0[c];
                    acc[0][1][r][c] += a0[r] * b1[c];
                    acc[1][0][r][c] += a1[r] * b0[c];
                    acc[1][1][r][c] += a1[r] * b1[c];
                }
        }
    }
#pragma unroll
    for (int a = 0; a < 2; a++)
#pragma unroll
        for (int r = 0; r < 4; r++) {
            size_t i = (size_t)(i0 + a * 64 + ty * 4 + r);
            float4 v0 = make_float4(acc[a][0][r][0], acc[a][0][r][1], acc[a][0][r][2], acc[a][0][r][3]);
            float4 v1 = make_float4(acc[a][1][r][0], acc[a][1][r][1], acc[a][1][r][2], acc[a][1][r][3]);
            *(float4*)(g_S + i * NN + j0 + tx * 4)      = v0;
            *(float4*)(g_S + i * NN + j0 + 64 + tx * 4) = v1;
        }
}

// ---------------- K3: partial column sums of exp(S) ---------------------------
// |S| < 64 strictly (tanh outputs), so exp(S) and its sums stay in fp32 range;
// skipping max-subtraction is mathematically identical to the reference softmax.
__global__ void k_colsum() {
    int j  = blockIdx.x * 256 + threadIdx.x;
    int r0 = blockIdx.y * 256;
    const float* p = g_S + (size_t)r0 * NN + j;
    float d = 0.f;
    for (int r = 0; r < 256; r += 8) {
        float v[8];
#pragma unroll
        for (int u = 0; u < 8; u++) v[u] = p[(size_t)(r + u) * NN];
#pragma unroll
        for (int u = 0; u < 8; u++) d += __expf(v[u]);
    }
    g_dpart[blockIdx.y * NN + j] = d;
}

__global__ void k_invd() {
    int j = blockIdx.x * 256 + threadIdx.x;
    float d = 0.f;
#pragma unroll
    for (int s = 0; s < 32; s++) d += g_dpart[s * NN + j];
    g_invD[j] = 1.0f / d;
}

// ---------------- K4: out = exp(S) @ (xe * invD), K split into 8 slices -------
__global__ __launch_bounds__(256) void k_av() {
    __shared__ float Ps[32][SPAD];   // [j][i] exp(S) tile, transposed
    __shared__ float vs[32][72];     // [j][f] scaled value tile
    const int i0    = blockIdx.x * 128;
    const int jbase = blockIdx.y * 1024;
    const int t  = threadIdx.x;
    const int tx = t & 15, ty = t >> 4;
    const int jf4 = t & 7, rr = t >> 3;

    float acc[2][4][4];
#pragma unroll
    for (int a = 0; a < 2; a++)
#pragma unroll
        for (int r = 0; r < 4; r++)
#pragma unroll
            for (int c = 0; c < 4; c++) acc[a][r][c] = 0.f;

    for (int ch = 0; ch < 32; ch++) {
        int j0 = jbase + ch * 32;
        __syncthreads();
#pragma unroll
        for (int l = 0; l < 4; l++) {
            int row = rr + l * 32;
            float4 s = *(const float4*)(g_S + (size_t)(i0 + row) * NN + j0 + jf4 * 4);
            Ps[jf4 * 4 + 0][row] = __expf(s.x);
            Ps[jf4 * 4 + 1][row] = __expf(s.y);
            Ps[jf4 * 4 + 2][row] = __expf(s.z);
            Ps[jf4 * 4 + 3][row] = __expf(s.w);
        }
#pragma unroll
        for (int l = 0; l < 2; l++) {
            int q = t + l * 256;
            int jj = q >> 4, fp = q & 15;
            float inv = __ldg(g_invD + j0 + jj);
            float4 v = *(const float4*)(g_xe + (size_t)(j0 + jj) * FF + fp * 4);
            v.x *= inv; v.y *= inv; v.z *= inv; v.w *= inv;
            *(float4*)&vs[jj][fp * 4] = v;
        }
        __syncthreads();
#pragma unroll 4
        for (int jj = 0; jj < 32; jj++) {
            float p0[4], p1[4], vv[4];
            *(float4*)p0 = *(const float4*)&Ps[jj][ty * 4];
            *(float4*)p1 = *(const float4*)&Ps[jj][64 + ty * 4];
            *(float4*)vv = *(const float4*)&vs[jj][tx * 4];
#pragma unroll
            for (int r = 0; r < 4; r++)
#pragma unroll
                for (int c = 0; c < 4; c++) {
                    acc[0][r][c] += p0[r] * vv[c];
                    acc[1][r][c] += p1[r] * vv[c];
                }
        }
    }
    float* op = g_outpart + (size_t)blockIdx.y * NN * FF;
#pragma unroll
    for (int a = 0; a < 2; a++)
#pragma unroll
        for (int r = 0; r < 4; r++) {
            float4 v = make_float4(acc[a][r][0], acc[a][r][1], acc[a][r][2], acc[a][r][3]);
            *(float4*)(op + (size_t)(i0 + a * 64 + ty * 4 + r) * FF + tx * 4) = v;
        }
}

// ---------------- K4r: deterministic reduction of the 8 K-slices --------------
__global__ void k_reduce_out(float* __restrict__ out) {
    int q = blockIdx.x * 256 + threadIdx.x;      // float4 index < NN*FF/4
    float4 s = ((const float4*)g_outpart)[q];
#pragma unroll
    for (int p = 1; p < 8; p++) {
        float4 v = ((const float4*)(g_outpart + (size_t)p * NN * FF))[q];
        s.x += v.x; s.y += v.y; s.z += v.z; s.w += v.w;
    }
    ((float4*)out)[q] = s;
}

// ---------------- K5a: row sum-of-squares + column sums (partials) ------------
__global__ void k_stats(const float* __restrict__ out) {
    __shared__ float sh[256];
    int b = blockIdx.x, t = threadIdx.x;
    // phase A: per-row sum of squares
    const float4* row = (const float4*)(out + (size_t)(b * 256 + t) * FF);
    float ss = 0.f;
#pragma unroll
    for (int i = 0; i < 16; i++) {
        float4 v = row[i];
        ss += v.x * v.x + v.y * v.y + v.z * v.z + v.w * v.w;
    }
    sh[t] = ss;
    __syncthreads();
    for (int s = 128; s > 0; s >>= 1) {
        if (t < s) sh[t] += sh[t + s];
        __syncthreads();
    }
    if (t == 0) g_sumsq_part[b] = sh[0];
    __syncthreads();
    // phase B: column sums over this block's 256 rows
    int f = t & 63, g = t >> 6;
    float cs = 0.f;
    for (int r = 0; r < 64; r++) cs += out[(size_t)(b * 256 + g * 64 + r) * FF + f];
    sh[t] = cs;
    __syncthreads();
    if (t < 64) g_colsum_part[b * FF + t] = sh[t] + sh[t + 64] + sh[t + 128] + sh[t + 192];
}

// ---------------- K5b: final mean(E) + alpha/beta MLPs ------------------------
__global__ void k_final(float* __restrict__ out,
                        const float* __restrict__ wa1, const float* __restrict__ ba1,
                        const float* __restrict__ wa2, const float* __restrict__ ba2,
                        const float* __restrict__ wb1, const float* __restrict__ bb1,
                        const float* __restrict__ wb2, const float* __restrict__ bb2) {
    __shared__ float sh[64];
    int t = threadIdx.x;                 // 64 threads
    float cs = 0.f;
    for (int b = 0; b < 32; b++) cs += g_colsum_part[b * FF + t];
    sh[t] = cs * cs;
    __syncthreads();
    if (t == 0) {
        float s2 = 0.f;
        for (int i = 0; i < 64; i++) s2 += sh[i];
        float sq = 0.f;
        for (int b = 0; b < 32; b++) sq += g_sumsq_part[b];
        // mean(E) = 2*mean_i(sq_i) - (2/N^2) * sum_f colsum_f^2
        float m = 2.0f * sq / (float)NN - 2.0f * s2 / ((float)NN * (float)NN);
        // alpha MLP: 1->2->1, tanh after every linear
        float ha0 = tanhf(m * __ldg(wa1 + 0) + __ldg(ba1 + 0));
        float ha1 = tanhf(m * __ldg(wa1 + 1) + __ldg(ba1 + 1));
        float ao  = tanhf(ha0 * __ldg(wa2 + 0) + ha1 * __ldg(wa2 + 1) + __ldg(ba2));
        // beta MLP
        float hb0 = tanhf(m * __ldg(wb1 + 0) + __ldg(bb1 + 0));
        float hb1 = tanhf(m * __ldg(wb1 + 1) + __ldg(bb1 + 1));
        float bo  = tanhf(hb0 * __ldg(wb2 + 0) + hb1 * __ldg(wb2 + 1) + __ldg(bb2));
        out[NN * FF]     = expf(SLOPEC * ao);
        out[NN * FF + 1] = expf(-SLOPEC * bo);
    }
}

// ---------------- launch ------------------------------------------------------
extern "C" void kernel_launch(void* const* d_in, const int* in_sizes, int n_in,
                              void* d_out, int out_size) {
    const float* x     = (const float*)d_in[0];
    const float* w_in1 = (const float*)d_in[1];
    const float* b_in1 = (const float*)d_in[2];
    const float* w_in2 = (const float*)d_in[3];
    const float* b_in2 = (const float*)d_in[4];
    const float* w_in3 = (const float*)d_in[5];
    const float* b_in3 = (const float*)d_in[6];
    const float* w_a1  = (const float*)d_in[7];
    const float* b_a1  = (const float*)d_in[8];
    const float* w_a2  = (const float*)d_in[9];
    const float* b_a2  = (const float*)d_in[10];
    const float* w_b1  = (const float*)d_in[11];
    const float* b_b1  = (const float*)d_in[12];
    const float* w_b2  = (const float*)d_in[13];
    const float* b_b2  = (const float*)d_in[14];
    float* out = (float*)d_out;

    k_encode<<<NN * FF / 256, 256>>>(x, w_in1, b_in1, w_in2, b_in2, w_in3, b_in3);
    k_gemm_s<<<dim3(64, 64), 256>>>();
    k_colsum<<<dim3(32, 32), 256>>>();
    k_invd<<<32, 256>>>();
    k_av<<<dim3(64, 8), 256>>>();
    k_reduce_out<<<NN * FF / 4 / 256, 256>>>(out);
    k_stats<<<32, 256>>>(out);
    k_final<<<1, 64>>>(out, w_a1, b_a1, w_a2, b_a2, w_b1, b_b1, w_b2, b_b2);
}

// round 16
// speedup vs baseline: 1.9527x; 1.9503x over previous
#include <cuda_runtime.h>
#include <cuda_bf16.h>
#include <cstdint>
#include <math.h>

#define NN 8192
#define FF 64
#define SLOPEC 3.0f

// ---------------- scratch (device globals; no allocations allowed) -------------
__device__ float g_xe[NN * FF];
__device__ __align__(16) __nv_bfloat16 g_xh[NN * FF];
__device__ __align__(16) __nv_bfloat16 g_xl[NN * FF];
__device__ __align__(16) __nv_bfloat16 g_Ph[(size_t)NN * NN];   // 128 MB  exp(S) hi
__device__ __align__(16) __nv_bfloat16 g_Pl[(size_t)NN * NN];   // 128 MB  exp(S) lo
__device__ __align__(16) __nv_bfloat16 g_Vh[FF * NN];           // [f][j] = xe[j][f]*invD[j] hi
__device__ __align__(16) __nv_bfloat16 g_Vl[FF * NN];
__device__ float g_dpart[32 * NN];
__device__ float g_invD[NN];
__device__ float g_outpart[4 * NN * FF];
__device__ float g_colsum_part[32 * FF];
__device__ float g_sumsq_part[32];

// ---------------- helpers ------------------------------------------------------
__device__ __forceinline__ uint32_t smem_u32(const void* p) {
    uint32_t a;
    asm("{ .reg .u64 t; cvta.to.shared.u64 t, %1; cvt.u32.u64 %0, t; }" : "=r"(a) : "l"(p));
    return a;
}
__device__ __forceinline__ void cp16(uint32_t d, const void* g) {
    asm volatile("cp.async.cg.shared.global [%0], [%1], 16;" :: "r"(d), "l"(g));
}
__device__ __forceinline__ void cp_commit() {
    asm volatile("cp.async.commit_group;" ::: "memory");
}
__device__ __forceinline__ void cp_wait1() {
    asm volatile("cp.async.wait_group 1;" ::: "memory");
}
__device__ __forceinline__ void cp_wait0() {
    asm volatile("cp.async.wait_group 0;" ::: "memory");
}
// warp-level bf16 MMA: D(16x8,f32) += A(16x16,bf16,row) * B(16x8,bf16,col)
__device__ __forceinline__ void mma_bf16(float* c, const uint32_t* a, const uint32_t* b) {
    asm volatile(
        "mma.sync.aligned.m16n8k16.row.col.f32.bf16.bf16.f32 "
        "{%0,%1,%2,%3}, {%4,%5,%6,%7}, {%8,%9}, {%0,%1,%2,%3};"
        : "+f"(c[0]), "+f"(c[1]), "+f"(c[2]), "+f"(c[3])
        : "r"(a[0]), "r"(a[1]), "r"(a[2]), "r"(a[3]), "r"(b[0]), "r"(b[1]));
}
__device__ __forceinline__ uint32_t pack_bf2(__nv_bfloat16 a, __nv_bfloat16 b) {
    __nv_bfloat162 v = __halves2bfloat162(a, b);
    return *reinterpret_cast<uint32_t*>(&v);
}
__device__ __forceinline__ void split2(float p, __nv_bfloat16& h, __nv_bfloat16& l) {
    h = __float2bfloat16(p);
    l = __float2bfloat16(p - __bfloat162float(h));
}

// ---------------- K1: encoder MLP 2->4->4->1 + hi/lo split --------------------
__global__ void k_encode(const float* __restrict__ x,
                         const float* __restrict__ w1, const float* __restrict__ b1,
                         const float* __restrict__ w2, const float* __restrict__ b2,
                         const float* __restrict__ w3, const float* __restrict__ b3) {
    int idx = blockIdx.x * 256 + threadIdx.x;
    float2 xv = ((const float2*)x)[idx];
    float h1[4], h2[4];
#pragma unroll
    for (int j = 0; j < 4; j++)
        h1[j] = tanhf(xv.x * __ldg(w1 + j) + xv.y * __ldg(w1 + 4 + j) + __ldg(b1 + j));
#pragma unroll
    for (int j = 0; j < 4; j++)
        h2[j] = tanhf(h1[0] * __ldg(w2 + j) + h1[1] * __ldg(w2 + 4 + j) +
                      h1[2] * __ldg(w2 + 8 + j) + h1[3] * __ldg(w2 + 12 + j) + __ldg(b2 + j));
    float o = tanhf(h2[0] * __ldg(w3 + 0) + h2[1] * __ldg(w3 + 1) +
                    h2[2] * __ldg(w3 + 2) + h2[3] * __ldg(w3 + 3) + __ldg(b3));
    g_xe[idx] = o;
    __nv_bfloat16 h, l;
    split2(o, h, l);
    g_xh[idx] = h;
    g_xl[idx] = l;
}

// ---------------- GEMM1: P = exp(xe xe^T) upper-triangle tiles, HMMA ----------
// tile 128x128, K=64, hi/lo split (3 terms). 8 warps: 2(m)x4(n), warp 64x32.
// smem A/B tiles stride 72 bf16 (144 B): conflict-free frag loads.
// Epilogue stages exp() results (bf16 hi/lo) in smem (stride 136 bf16 = 272 B)
// for fully coalesced stores; off-diagonal tiles re-stage transposed.
#define G1_SMEM 73728
__global__ __launch_bounds__(256) void k_gemm1() {
    extern __shared__ __align__(16) char sm[];
    const int bx = blockIdx.x, by = blockIdx.y;
    if (by > bx) return;                      // upper triangle incl. diagonal
    const int i0 = by * 128, j0 = bx * 128;
    const int t = threadIdx.x, wid = t >> 5, lid = t & 31;
    const int g = lid >> 2, tg = lid & 3;
    const int wm = (wid >> 2) * 64, wn = (wid & 3) * 32;
    const int AhO = 0, AlO = 18432, BhO = 36864, BlO = 55296;

    const uint4* xh4 = (const uint4*)g_xh;
    const uint4* xl4 = (const uint4*)g_xl;
#pragma unroll
    for (int l = 0; l < 4; l++) {
        int idx = t + l * 256, row = idx >> 3, q = idx & 7;
        int d = row * 144 + q * 16;
        *(uint4*)(sm + AhO + d) = xh4[(size_t)(i0 + row) * 8 + q];
        *(uint4*)(sm + AlO + d) = xl4[(size_t)(i0 + row) * 8 + q];
        *(uint4*)(sm + BhO + d) = xh4[(size_t)(j0 + row) * 8 + q];
        *(uint4*)(sm + BlO + d) = xl4[(size_t)(j0 + row) * 8 + q];
    }
    __syncthreads();

    float acc[4][4][4];
#pragma unroll
    for (int mt = 0; mt < 4; mt++)
#pragma unroll
        for (int nt = 0; nt < 4; nt++)
#pragma unroll
            for (int r = 0; r < 4; r++) acc[mt][nt][r] = 0.f;

#pragma unroll
    for (int term = 0; term < 3; term++) {    // hh, hl, lh
        const char* Ab = sm + ((term == 2) ? AlO : AhO);
        const char* Bb = sm + ((term == 1) ? BlO : BhO);
#pragma unroll
        for (int ks = 0; ks < 4; ks++) {
            const int kb = ks * 32 + tg * 4;  // byte offset of k element
            uint32_t a[4][4], b[4][2];
#pragma unroll
            for (int mt = 0; mt < 4; mt++) {
                const char* p = Ab + (wm + mt * 16 + g) * 144 + kb;
                a[mt][0] = *(const uint32_t*)p;
                a[mt][1] = *(const uint32_t*)(p + 8 * 144);
                a[mt][2] = *(const uint32_t*)(p + 16);
                a[mt][3] = *(const uint32_t*)(p + 8 * 144 + 16);
            }
#pragma unroll
            for (int nt = 0; nt < 4; nt++) {
                const char* p = Bb + (wn + nt * 8 + g) * 144 + kb;
                b[nt][0] = *(const uint32_t*)p;
                b[nt][1] = *(const uint32_t*)(p + 16);
            }
#pragma unroll
            for (int mt = 0; mt < 4; mt++)
#pragma unroll
                for (int nt = 0; nt < 4; nt++)
                    mma_bf16(acc[mt][nt], a[mt], b[nt]);
        }
    }
    __syncthreads();                          // done with A/B smem

    // ---- pass 1: normal-orientation staging + coalesced store ----
    const int PhS = 0, PlS = 34816;           // stride 272 B
#pragma unroll
    for (int mt = 0; mt < 4; mt++)
#pragma unroll
        for (int nt = 0; nt < 4; nt++) {
            __nv_bfloat16 h0, h1, h2, h3, l0, l1, l2, l3;
            split2(__expf(acc[mt][nt][0]), h0, l0);
            split2(__expf(acc[mt][nt][1]), h1, l1);
            split2(__expf(acc[mt][nt][2]), h2, l2);
            split2(__expf(acc[mt][nt][3]), h3, l3);
            int r0 = wm + mt * 16 + g, c0 = wn + nt * 8 + tg * 2;
            *(uint32_t*)(sm + PhS + r0 * 272 + c0 * 2)       = pack_bf2(h0, h1);
            *(uint32_t*)(sm + PhS + (r0 + 8) * 272 + c0 * 2) = pack_bf2(h2, h3);
            *(uint32_t*)(sm + PlS + r0 * 272 + c0 * 2)       = pack_bf2(l0, l1);
            *(uint32_t*)(sm + PlS + (r0 + 8) * 272 + c0 * 2) = pack_bf2(l2, l3);
        }
    __syncthreads();
#pragma unroll
    for (int l = 0; l < 8; l++) {
        int idx = t + l * 256, row = idx >> 4, ch = idx & 15;
        *(uint4*)(g_Ph + (size_t)(i0 + row) * NN + j0 + ch * 8) =
            *(const uint4*)(sm + PhS + row * 272 + ch * 16);
        *(uint4*)(g_Pl + (size_t)(i0 + row) * NN + j0 + ch * 8) =
            *(const uint4*)(sm + PlS + row * 272 + ch * 16);
    }
    if (bx == by) return;

    // ---- pass 2: transposed staging + coalesced store to (j0, i0) ----
    __syncthreads();
#pragma unroll
    for (int mt = 0; mt < 4; mt++)
#pragma unroll
        for (int nt = 0; nt < 4; nt++) {
            __nv_bfloat16 h0, h1, h2, h3, l0, l1, l2, l3;
            split2(__expf(acc[mt][nt][0]), h0, l0);
            split2(__expf(acc[mt][nt][1]), h1, l1);
            split2(__expf(acc[mt][nt][2]), h2, l2);
            split2(__expf(acc[mt][nt][3]), h3, l3);
            int r0 = wm + mt * 16 + g, c0 = wn + nt * 8 + tg * 2;
            *(__nv_bfloat16*)(sm + PhS + c0 * 272 + r0 * 2)             = h0;
            *(__nv_bfloat16*)(sm + PhS + (c0 + 1) * 272 + r0 * 2)       = h1;
            *(__nv_bfloat16*)(sm + PhS + c0 * 272 + (r0 + 8) * 2)       = h2;
            *(__nv_bfloat16*)(sm + PhS + (c0 + 1) * 272 + (r0 + 8) * 2) = h3;
            *(__nv_bfloat16*)(sm + PlS + c0 * 272 + r0 * 2)             = l0;
            *(__nv_bfloat16*)(sm + PlS + (c0 + 1) * 272 + r0 * 2)       = l1;
            *(__nv_bfloat16*)(sm + PlS + c0 * 272 + (r0 + 8) * 2)       = l2;
            *(__nv_bfloat16*)(sm + PlS + (c0 + 1) * 272 + (r0 + 8) * 2) = l3;
        }
    __syncthreads();
#pragma unroll
    for (int l = 0; l < 8; l++) {
        int idx = t + l * 256, row = idx >> 4, ch = idx & 15;
        *(uint4*)(g_Ph + (size_t)(j0 + row) * NN + i0 + ch * 8) =
            *(const uint4*)(sm + PhS + row * 272 + ch * 16);
        *(uint4*)(g_Pl + (size_t)(j0 + row) * NN + i0 + ch * 8) =
            *(const uint4*)(sm + PlS + row * 272 + ch * 16);
    }
}

// ---------------- K3: column sums of P (Ph only; row-averaging kills noise) ---
__global__ void k_colsum() {
    int j = blockIdx.x * 256 + threadIdx.x;
    int r0 = blockIdx.y * 256;
    const __nv_bfloat16* p = g_Ph + (size_t)r0 * NN + j;
    float d = 0.f;
    for (int r = 0; r < 256; r += 8) {
        float v[8];
#pragma unroll
        for (int u = 0; u < 8; u++) v[u] = __bfloat162float(p[(size_t)(r + u) * NN]);
#pragma unroll
        for (int u = 0; u < 8; u++) d += v[u];
    }
    g_dpart[blockIdx.y * NN + j] = d;
}

__global__ void k_invd() {
    int j = blockIdx.x * 256 + threadIdx.x;
    float d = 0.f;
#pragma unroll
    for (int s = 0; s < 32; s++) d += g_dpart[s * NN + j];
    g_invD[j] = 1.0f / d;
}

// ---------------- prepV: Vt[f][j] = xe[j][f]*invD[j], hi/lo bf16 --------------
__global__ void k_prepV() {
    __shared__ float tile[64][65];
    int jb = blockIdx.x * 64;
    int t = threadIdx.x;     // 256
#pragma unroll
    for (int l = 0; l < 16; l++) {
        int idx = t + l * 256, j = idx >> 6, f = idx & 63;
        tile[j][f] = g_xe[(size_t)(jb + j) * FF + f] * g_invD[jb + j];
    }
    __syncthreads();
#pragma unroll
    for (int l = 0; l < 16; l++) {
        int idx = t + l * 256, f = idx >> 6, j = idx & 63;
        __nv_bfloat16 h, lo;
        split2(tile[j][f], h, lo);
        g_Vh[(size_t)f * NN + jb + j] = h;
        g_Vl[(size_t)f * NN + jb + j] = lo;
    }
}

// ---------------- GEMM2: out = (Ph+Pl) @ (Vh+Vl), cp.async pipelined ----------
// block tile 128(m) x 64(n), K chunks of 64, double-buffered. 8 warps 4(m)x2(n).
#define G2_BUF 55296
#define G2_SMEM (2 * G2_BUF)
__device__ __forceinline__ void g2_pf(uint32_t sb, int i0, int j0, int t) {
#pragma unroll
    for (int l = 0; l < 4; l++) {
        int idx = t + l * 256, row = idx >> 3, q = idx & 7;
        uint32_t d = sb + row * 144 + q * 16;
        cp16(d,         g_Ph + (size_t)(i0 + row) * NN + j0 + q * 8);
        cp16(d + 18432, g_Pl + (size_t)(i0 + row) * NN + j0 + q * 8);
    }
#pragma unroll
    for (int l = 0; l < 2; l++) {
        int idx = t + l * 256, row = idx >> 3, q = idx & 7;   // row = f in 0..63
        uint32_t d = sb + 36864 + row * 144 + q * 16;
        cp16(d,        g_Vh + (size_t)row * NN + j0 + q * 8);
        cp16(d + 9216, g_Vl + (size_t)row * NN + j0 + q * 8);
    }
}

__global__ __launch_bounds__(256) void k_gemm2() {
    extern __shared__ __align__(16) char sm[];
    const uint32_t sb = smem_u32(sm);
    const int t = threadIdx.x, wid = t >> 5, lid = t & 31;
    const int g = lid >> 2, tg = lid & 3;
    const int i0 = blockIdx.x * 128, jbase = blockIdx.y * 2048;
    const int wm = (wid >> 1) * 32, wn = (wid & 1) * 32;

    float acc[2][4][4];
#pragma unroll
    for (int mt = 0; mt < 2; mt++)
#pragma unroll
        for (int nt = 0; nt < 4; nt++)
#pragma unroll
            for (int r = 0; r < 4; r++) acc[mt][nt][r] = 0.f;

    g2_pf(sb, i0, jbase, t);
    cp_commit();

#pragma unroll 1
    for (int ch = 0; ch < 32; ch++) {
        if (ch + 1 < 32) {
            g2_pf(sb + ((ch + 1) & 1) * G2_BUF, i0, jbase + (ch + 1) * 64, t);
            cp_commit();
            cp_wait1();
        } else {
            cp_wait0();
        }
        __syncthreads();
        const char* buf = sm + (ch & 1) * G2_BUF;
#pragma unroll
        for (int term = 0; term < 3; term++) {    // PhVh, PhVl, PlVh
            const char* Pb = buf + ((term == 2) ? 18432 : 0);
            const char* Vb = buf + 36864 + ((term == 1) ? 9216 : 0);
#pragma unroll
            for (int ks = 0; ks < 4; ks++) {
                const int kb = ks * 32 + tg * 4;
                uint32_t a[2][4], b[4][2];
#pragma unroll
                for (int mt = 0; mt < 2; mt++) {
                    const char* p = Pb + (wm + mt * 16 + g) * 144 + kb;
                    a[mt][0] = *(const uint32_t*)p;
                    a[mt][1] = *(const uint32_t*)(p + 8 * 144);
                    a[mt][2] = *(const uint32_t*)(p + 16);
                    a[mt][3] = *(const uint32_t*)(p + 8 * 144 + 16);
                }
#pragma unroll
                for (int nt = 0; nt < 4; nt++) {
                    const char* p = Vb + (wn + nt * 8 + g) * 144 + kb;
                    b[nt][0] = *(const uint32_t*)p;
                    b[nt][1] = *(const uint32_t*)(p + 16);
                }
#pragma unroll
                for (int mt = 0; mt < 2; mt++)
#pragma unroll
                    for (int nt = 0; nt < 4; nt++)
                        mma_bf16(acc[mt][nt], a[mt], b[nt]);
            }
        }
        __syncthreads();
    }

    float* op = g_outpart + (size_t)blockIdx.y * NN * FF;
#pragma unroll
    for (int mt = 0; mt < 2; mt++)
#pragma unroll
        for (int nt = 0; nt < 4; nt++) {
            int r0 = i0 + wm + mt * 16 + g, c0 = wn + nt * 8 + tg * 2;
            *(float2*)(op + (size_t)r0 * FF + c0) =
                make_float2(acc[mt][nt][0], acc[mt][nt][1]);
            *(float2*)(op + (size_t)(r0 + 8) * FF + c0) =
                make_float2(acc[mt][nt][2], acc[mt][nt][3]);
        }
}

// ---------------- reduce 4 K-slices -------------------------------------------
__global__ void k_reduce_out(float* __restrict__ out) {
    int q = blockIdx.x * 256 + threadIdx.x;
    float4 s = ((const float4*)g_outpart)[q];
#pragma unroll
    for (int p = 1; p < 4; p++) {
        float4 v = ((const float4*)(g_outpart + (size_t)p * NN * FF))[q];
        s.x += v.x; s.y += v.y; s.z += v.z; s.w += v.w;
    }
    ((float4*)out)[q] = s;
}

// ---------------- stats + final -----------------------------------------------
__global__ void k_stats(const float* __restrict__ out) {
    __shared__ float sh[256];
    int b = blockIdx.x, t = threadIdx.x;
    const float4* row = (const float4*)(out + (size_t)(b * 256 + t) * FF);
    float ss = 0.f;
#pragma unroll
    for (int i = 0; i < 16; i++) {
        float4 v = row[i];
        ss += v.x * v.x + v.y * v.y + v.z * v.z + v.w * v.w;
    }
    sh[t] = ss;
    __syncthreads();
    for (int s = 128; s > 0; s >>= 1) {
        if (t < s) sh[t] += sh[t + s];
        __syncthreads();
    }
    if (t == 0) g_sumsq_part[b] = sh[0];
    __syncthreads();
    int f = t & 63, g = t >> 6;
    float cs = 0.f;
    for (int r = 0; r < 64; r++) cs += out[(size_t)(b * 256 + g * 64 + r) * FF + f];
    sh[t] = cs;
    __syncthreads();
    if (t < 64) g_colsum_part[b * FF + t] = sh[t] + sh[t + 64] + sh[t + 128] + sh[t + 192];
}

__global__ void k_final(float* __restrict__ out,
                        const float* __restrict__ wa1, const float* __restrict__ ba1,
                        const float* __restrict__ wa2, const float* __restrict__ ba2,
                        const float* __restrict__ wb1, const float* __restrict__ bb1,
                        const float* __restrict__ wb2, const float* __restrict__ bb2) {
    __shared__ float sh[64];
    int t = threadIdx.x;
    float cs = 0.f;
    for (int b = 0; b < 32; b++) cs += g_colsum_part[b * FF + t];
    sh[t] = cs * cs;
    __syncthreads();
    if (t == 0) {
        float s2 = 0.f;
        for (int i = 0; i < 64; i++) s2 += sh[i];
        float sq = 0.f;
        for (int b = 0; b < 32; b++) sq += g_sumsq_part[b];
        float m = 2.0f * sq / (float)NN - 2.0f * s2 / ((float)NN * (float)NN);
        float ha0 = tanhf(m * __ldg(wa1 + 0) + __ldg(ba1 + 0));
        float ha1 = tanhf(m * __ldg(wa1 + 1) + __ldg(ba1 + 1));
        float ao  = tanhf(ha0 * __ldg(wa2 + 0) + ha1 * __ldg(wa2 + 1) + __ldg(ba2));
        float hb0 = tanhf(m * __ldg(wb1 + 0) + __ldg(bb1 + 0));
        float hb1 = tanhf(m * __ldg(wb1 + 1) + __ldg(bb1 + 1));
        float bo  = tanhf(hb0 * __ldg(wb2 + 0) + hb1 * __ldg(wb2 + 1) + __ldg(bb2));
        out[NN * FF]     = expf(SLOPEC * ao);
        out[NN * FF + 1] = expf(-SLOPEC * bo);
    }
}

// ---------------- launch ------------------------------------------------------
extern "C" void kernel_launch(void* const* d_in, const int* in_sizes, int n_in,
                              void* d_out, int out_size) {
    const float* x     = (const float*)d_in[0];
    const float* w_in1 = (const float*)d_in[1];
    const float* b_in1 = (const float*)d_in[2];
    const float* w_in2 = (const float*)d_in[3];
    const float* b_in2 = (const float*)d_in[4];
    const float* w_in3 = (const float*)d_in[5];
    const float* b_in3 = (const float*)d_in[6];
    const float* w_a1  = (const float*)d_in[7];
    const float* b_a1  = (const float*)d_in[8];
    const float* w_a2  = (const float*)d_in[9];
    const float* b_a2  = (const float*)d_in[10];
    const float* w_b1  = (const float*)d_in[11];
    const float* b_b1  = (const float*)d_in[12];
    const float* w_b2  = (const float*)d_in[13];
    const float* b_b2  = (const float*)d_in[14];
    float* out = (float*)d_out;

    cudaFuncSetAttribute(k_gemm1, cudaFuncAttributeMaxDynamicSharedMemorySize, G1_SMEM);
    cudaFuncSetAttribute(k_gemm2, cudaFuncAttributeMaxDynamicSharedMemorySize, G2_SMEM);

    k_encode<<<NN * FF / 256, 256>>>(x, w_in1, b_in1, w_in2, b_in2, w_in3, b_in3);
    k_gemm1<<<dim3(64, 64), 256, G1_SMEM>>>();
    k_colsum<<<dim3(32, 32), 256>>>();
    k_invd<<<32, 256>>>();
    k_prepV<<<NN / 64, 256>>>();
    k_gemm2<<<dim3(64, 4), 256, G2_SMEM>>>();
    k_reduce_out<<<NN * FF / 4 / 256, 256>>>(out);
    k_stats<<<32, 256>>>(out);
    k_final<<<1, 64>>>(out, w_a1, b_a1, w_a2, b_a2, w_b1, b_b1, w_b2, b_b2);
}

// round 17
// speedup vs baseline: 2.9471x; 1.5092x over previous
#include <cuda_runtime.h>
#include <cuda_bf16.h>
#include <cstdint>
#include <math.h>

#define NN 8192
#define FF 64
#define SLOPEC 3.0f

// ---------------- scratch (device globals; no allocations allowed) -------------
__device__ float g_xe[NN * FF];
__device__ __align__(16) __nv_bfloat16 g_xh[NN * FF];
__device__ __align__(16) __nv_bfloat16 g_xl[NN * FF];
__device__ __align__(16) __nv_bfloat16 g_Ph[(size_t)NN * NN];   // 128 MB  exp(S) bf16
__device__ __align__(16) __nv_bfloat16 g_Vh[FF * NN];           // [f][j] = xe[j][f]*invD[j] hi
__device__ __align__(16) __nv_bfloat16 g_Vl[FF * NN];
__device__ float g_dpart[64 * NN];                              // per-rowblock colsum partials
__device__ float g_invD[NN];
__device__ float g_outpart[4 * NN * FF];
__device__ float g_colsum_part[32 * FF];
__device__ float g_sumsq_part[32];

// ---------------- helpers ------------------------------------------------------
__device__ __forceinline__ uint32_t smem_u32(const void* p) {
    uint32_t a;
    asm("{ .reg .u64 t; cvta.to.shared.u64 t, %1; cvt.u32.u64 %0, t; }" : "=r"(a) : "l"(p));
    return a;
}
__device__ __forceinline__ void cp16(uint32_t d, const void* g) {
    asm volatile("cp.async.cg.shared.global [%0], [%1], 16;" :: "r"(d), "l"(g));
}
__device__ __forceinline__ void cp_commit() {
    asm volatile("cp.async.commit_group;" ::: "memory");
}
__device__ __forceinline__ void cp_wait1() {
    asm volatile("cp.async.wait_group 1;" ::: "memory");
}
__device__ __forceinline__ void cp_wait0() {
    asm volatile("cp.async.wait_group 0;" ::: "memory");
}
// warp-level bf16 MMA: D(16x8,f32) += A(16x16,bf16,row) * B(16x8,bf16,col)
__device__ __forceinline__ void mma_bf16(float* c, const uint32_t* a, const uint32_t* b) {
    asm volatile(
        "mma.sync.aligned.m16n8k16.row.col.f32.bf16.bf16.f32 "
        "{%0,%1,%2,%3}, {%4,%5,%6,%7}, {%8,%9}, {%0,%1,%2,%3};"
        : "+f"(c[0]), "+f"(c[1]), "+f"(c[2]), "+f"(c[3])
        : "r"(a[0]), "r"(a[1]), "r"(a[2]), "r"(a[3]), "r"(b[0]), "r"(b[1]));
}
__device__ __forceinline__ uint32_t pack_bf2(__nv_bfloat16 a, __nv_bfloat16 b) {
    __nv_bfloat162 v = __halves2bfloat162(a, b);
    return *reinterpret_cast<uint32_t*>(&v);
}
__device__ __forceinline__ void split2(float p, __nv_bfloat16& h, __nv_bfloat16& l) {
    h = __float2bfloat16(p);
    l = __float2bfloat16(p - __bfloat162float(h));
}

// ---------------- K1: encoder MLP 2->4->4->1 + hi/lo split --------------------
__global__ void k_encode(const float* __restrict__ x,
                         const float* __restrict__ w1, const float* __restrict__ b1,
                         const float* __restrict__ w2, const float* __restrict__ b2,
                         const float* __restrict__ w3, const float* __restrict__ b3) {
    int idx = blockIdx.x * 256 + threadIdx.x;
    float2 xv = ((const float2*)x)[idx];
    float h1[4], h2[4];
#pragma unroll
    for (int j = 0; j < 4; j++)
        h1[j] = tanhf(xv.x * __ldg(w1 + j) + xv.y * __ldg(w1 + 4 + j) + __ldg(b1 + j));
#pragma unroll
    for (int j = 0; j < 4; j++)
        h2[j] = tanhf(h1[0] * __ldg(w2 + j) + h1[1] * __ldg(w2 + 4 + j) +
                      h1[2] * __ldg(w2 + 8 + j) + h1[3] * __ldg(w2 + 12 + j) + __ldg(b2 + j));
    float o = tanhf(h2[0] * __ldg(w3 + 0) + h2[1] * __ldg(w3 + 1) +
                    h2[2] * __ldg(w3 + 2) + h2[3] * __ldg(w3 + 3) + __ldg(b3));
    g_xe[idx] = o;
    __nv_bfloat16 h, l;
    split2(o, h, l);
    g_xh[idx] = h;
    g_xl[idx] = l;
}

// ---------------- GEMM1: P = exp(xe xe^T), upper-tri tiles, fused colsums -----
// tile 128x128, K=64, hi/lo split (3 terms). 8 warps 2(m)x4(n), warp 64x32.
// Epilogue: fp32 column partials (both orientations) -> g_dpart; bf16 Ph store.
#define G1_SMEM 73728
__global__ __launch_bounds__(256) void k_gemm1() {
    extern __shared__ __align__(16) char sm[];
    const int bx = blockIdx.x, by = blockIdx.y;
    if (by > bx) return;                      // upper triangle incl. diagonal
    const int i0 = by * 128, j0 = bx * 128;
    const int t = threadIdx.x, wid = t >> 5, lid = t & 31;
    const int g = lid >> 2, tg = lid & 3;
    const int wm = (wid >> 2) * 64, wn = (wid & 3) * 32;
    const int AhO = 0, AlO = 18432, BhO = 36864, BlO = 55296;

    const uint4* xh4 = (const uint4*)g_xh;
    const uint4* xl4 = (const uint4*)g_xl;
#pragma unroll
    for (int l = 0; l < 4; l++) {
        int idx = t + l * 256, row = idx >> 3, q = idx & 7;
        int d = row * 144 + q * 16;
        *(uint4*)(sm + AhO + d) = xh4[(size_t)(i0 + row) * 8 + q];
        *(uint4*)(sm + AlO + d) = xl4[(size_t)(i0 + row) * 8 + q];
        *(uint4*)(sm + BhO + d) = xh4[(size_t)(j0 + row) * 8 + q];
        *(uint4*)(sm + BlO + d) = xl4[(size_t)(j0 + row) * 8 + q];
    }
    __syncthreads();

    float acc[4][4][4];
#pragma unroll
    for (int mt = 0; mt < 4; mt++)
#pragma unroll
        for (int nt = 0; nt < 4; nt++)
#pragma unroll
            for (int r = 0; r < 4; r++) acc[mt][nt][r] = 0.f;

#pragma unroll
    for (int term = 0; term < 3; term++) {    // hh, hl, lh
        const char* Ab = sm + ((term == 2) ? AlO : AhO);
        const char* Bb = sm + ((term == 1) ? BlO : BhO);
#pragma unroll
        for (int ks = 0; ks < 4; ks++) {
            const int kb = ks * 32 + tg * 4;
            uint32_t a[4][4], b[4][2];
#pragma unroll
            for (int mt = 0; mt < 4; mt++) {
                const char* p = Ab + (wm + mt * 16 + g) * 144 + kb;
                a[mt][0] = *(const uint32_t*)p;
                a[mt][1] = *(const uint32_t*)(p + 8 * 144);
                a[mt][2] = *(const uint32_t*)(p + 16);
                a[mt][3] = *(const uint32_t*)(p + 8 * 144 + 16);
            }
#pragma unroll
            for (int nt = 0; nt < 4; nt++) {
                const char* p = Bb + (wn + nt * 8 + g) * 144 + kb;
                b[nt][0] = *(const uint32_t*)p;
                b[nt][1] = *(const uint32_t*)(p + 16);
            }
#pragma unroll
            for (int mt = 0; mt < 4; mt++)
#pragma unroll
                for (int nt = 0; nt < 4; nt++)
                    mma_bf16(acc[mt][nt], a[mt], b[nt]);
        }
    }
    __syncthreads();                          // done with A/B smem

    // exp in place (fp32)
#pragma unroll
    for (int mt = 0; mt < 4; mt++)
#pragma unroll
        for (int nt = 0; nt < 4; nt++)
#pragma unroll
            for (int r = 0; r < 4; r++) acc[mt][nt][r] = __expf(acc[mt][nt][r]);

    const int PhS = 0;                        // stride 272 B
    const int CsO = 34816;                    // float cs[2][128]
    const int RsO = 35840;                    // float rs[2][4][64]
    float* csf = (float*)(sm + CsO);
    float* rsf = (float*)(sm + RsO);

    // ---- fused column-sum partials (this orientation: sum over i rows) ----
    {
        float colp[4][2];
#pragma unroll
        for (int nt = 0; nt < 4; nt++) {
            colp[nt][0] = colp[nt][1] = 0.f;
#pragma unroll
            for (int mt = 0; mt < 4; mt++) {
                colp[nt][0] += acc[mt][nt][0] + acc[mt][nt][2];
                colp[nt][1] += acc[mt][nt][1] + acc[mt][nt][3];
            }
        }
#pragma unroll
        for (int o = 16; o >= 4; o >>= 1)
#pragma unroll
            for (int nt = 0; nt < 4; nt++) {
                colp[nt][0] += __shfl_xor_sync(0xffffffffu, colp[nt][0], o);
                colp[nt][1] += __shfl_xor_sync(0xffffffffu, colp[nt][1], o);
            }
        if (lid < 4)
#pragma unroll
            for (int nt = 0; nt < 4; nt++) {
                csf[(wid >> 2) * 128 + wn + nt * 8 + tg * 2 + 0] = colp[nt][0];
                csf[(wid >> 2) * 128 + wn + nt * 8 + tg * 2 + 1] = colp[nt][1];
            }
    }
    // ---- row-sum partials (= colsums of transposed block, off-diag only) ----
    if (bx != by) {
        float rowp[4][2];
#pragma unroll
        for (int mt = 0; mt < 4; mt++) {
            rowp[mt][0] = rowp[mt][1] = 0.f;
#pragma unroll
            for (int nt = 0; nt < 4; nt++) {
                rowp[mt][0] += acc[mt][nt][0] + acc[mt][nt][1];
                rowp[mt][1] += acc[mt][nt][2] + acc[mt][nt][3];
            }
        }
#pragma unroll
        for (int o = 1; o <= 2; o <<= 1)
#pragma unroll
            for (int mt = 0; mt < 4; mt++) {
                rowp[mt][0] += __shfl_xor_sync(0xffffffffu, rowp[mt][0], o);
                rowp[mt][1] += __shfl_xor_sync(0xffffffffu, rowp[mt][1], o);
            }
        if (tg == 0)
#pragma unroll
            for (int mt = 0; mt < 4; mt++) {
                rsf[((wid >> 2) * 4 + (wid & 3)) * 64 + mt * 16 + g + 0] = rowp[mt][0];
                rsf[((wid >> 2) * 4 + (wid & 3)) * 64 + mt * 16 + g + 8] = rowp[mt][1];
            }
    }

    // ---- pass 1: normal-orientation bf16 staging ----
#pragma unroll
    for (int mt = 0; mt < 4; mt++)
#pragma unroll
        for (int nt = 0; nt < 4; nt++) {
            int r0 = wm + mt * 16 + g, c0 = wn + nt * 8 + tg * 2;
            *(uint32_t*)(sm + PhS + r0 * 272 + c0 * 2) =
                pack_bf2(__float2bfloat16(acc[mt][nt][0]), __float2bfloat16(acc[mt][nt][1]));
            *(uint32_t*)(sm + PhS + (r0 + 8) * 272 + c0 * 2) =
                pack_bf2(__float2bfloat16(acc[mt][nt][2]), __float2bfloat16(acc[mt][nt][3]));
        }
    __syncthreads();
#pragma unroll
    for (int l = 0; l < 8; l++) {
        int idx = t + l * 256, row = idx >> 4, ch = idx & 15;
        *(uint4*)(g_Ph + (size_t)(i0 + row) * NN + j0 + ch * 8) =
            *(const uint4*)(sm + PhS + row * 272 + ch * 16);
    }
    // colsum partials -> gmem
    if (t < 128) {
        g_dpart[(size_t)by * NN + j0 + t] = csf[t] + csf[128 + t];
    } else if (bx != by) {
        int r = t - 128, hf = r >> 6, lr = r & 63;
        g_dpart[(size_t)bx * NN + i0 + r] =
            rsf[(hf * 4 + 0) * 64 + lr] + rsf[(hf * 4 + 1) * 64 + lr] +
            rsf[(hf * 4 + 2) * 64 + lr] + rsf[(hf * 4 + 3) * 64 + lr];
    }
    if (bx == by) return;

    // ---- pass 2: transposed staging -> (j0, i0) tile ----
    __syncthreads();
#pragma unroll
    for (int mt = 0; mt < 4; mt++)
#pragma unroll
        for (int nt = 0; nt < 4; nt++) {
            int r0 = wm + mt * 16 + g, c0 = wn + nt * 8 + tg * 2;
            *(__nv_bfloat16*)(sm + PhS + c0 * 272 + r0 * 2)             = __float2bfloat16(acc[mt][nt][0]);
            *(__nv_bfloat16*)(sm + PhS + (c0 + 1) * 272 + r0 * 2)       = __float2bfloat16(acc[mt][nt][1]);
            *(__nv_bfloat16*)(sm + PhS + c0 * 272 + (r0 + 8) * 2)       = __float2bfloat16(acc[mt][nt][2]);
            *(__nv_bfloat16*)(sm + PhS + (c0 + 1) * 272 + (r0 + 8) * 2) = __float2bfloat16(acc[mt][nt][3]);
        }
    __syncthreads();
#pragma unroll
    for (int l = 0; l < 8; l++) {
        int idx = t + l * 256, row = idx >> 4, ch = idx & 15;
        *(uint4*)(g_Ph + (size_t)(j0 + row) * NN + i0 + ch * 8) =
            *(const uint4*)(sm + PhS + row * 272 + ch * 16);
    }
}

// ---------------- invD: reduce 64 partials ------------------------------------
__global__ void k_invd() {
    int j = blockIdx.x * 256 + threadIdx.x;
    float d = 0.f;
#pragma unroll 8
    for (int s = 0; s < 64; s++) d += g_dpart[(size_t)s * NN + j];
    g_invD[j] = 1.0f / d;
}

// ---------------- prepV: Vt[f][j] = xe[j][f]*invD[j], hi/lo bf16 --------------
__global__ void k_prepV() {
    __shared__ float tile[64][65];
    int jb = blockIdx.x * 64;
    int t = threadIdx.x;     // 256
#pragma unroll
    for (int l = 0; l < 16; l++) {
        int idx = t + l * 256, j = idx >> 6, f = idx & 63;
        tile[j][f] = g_xe[(size_t)(jb + j) * FF + f] * g_invD[jb + j];
    }
    __syncthreads();
#pragma unroll
    for (int l = 0; l < 16; l++) {
        int idx = t + l * 256, f = idx >> 6, j = idx & 63;
        __nv_bfloat16 h, lo;
        split2(tile[j][f], h, lo);
        g_Vh[(size_t)f * NN + jb + j] = h;
        g_Vl[(size_t)f * NN + jb + j] = lo;
    }
}

// ---------------- GEMM2: out = Ph @ (Vh+Vl), cp.async pipelined ---------------
// block tile 128(m) x 64(n), K chunks of 64, double-buffered. 8 warps 4(m)x2(n).
#define G2_BUF 36864
#define G2_SMEM (2 * G2_BUF)
__device__ __forceinline__ void g2_pf(uint32_t sb, int i0, int j0, int t) {
#pragma unroll
    for (int l = 0; l < 4; l++) {
        int idx = t + l * 256, row = idx >> 3, q = idx & 7;
        cp16(sb + row * 144 + q * 16, g_Ph + (size_t)(i0 + row) * NN + j0 + q * 8);
    }
#pragma unroll
    for (int l = 0; l < 2; l++) {
        int idx = t + l * 256, row = idx >> 3, q = idx & 7;   // row = f in 0..63
        uint32_t d = sb + 18432 + row * 144 + q * 16;
        cp16(d,        g_Vh + (size_t)row * NN + j0 + q * 8);
        cp16(d + 9216, g_Vl + (size_t)row * NN + j0 + q * 8);
    }
}

__global__ __launch_bounds__(256) void k_gemm2() {
    extern __shared__ __align__(16) char sm[];
    const uint32_t sb = smem_u32(sm);
    const int t = threadIdx.x, wid = t >> 5, lid = t & 31;
    const int g = lid >> 2, tg = lid & 3;
    const int i0 = blockIdx.x * 128, jbase = blockIdx.y * 2048;
    const int wm = (wid >> 1) * 32, wn = (wid & 1) * 32;

    float acc[2][4][4];
#pragma unroll
    for (int mt = 0; mt < 2; mt++)
#pragma unroll
        for (int nt = 0; nt < 4; nt++)
#pragma unroll
            for (int r = 0; r < 4; r++) acc[mt][nt][r] = 0.f;

    g2_pf(sb, i0, jbase, t);
    cp_commit();

#pragma unroll 1
    for (int ch = 0; ch < 32; ch++) {
        if (ch + 1 < 32) {
            g2_pf(sb + ((ch + 1) & 1) * G2_BUF, i0, jbase + (ch + 1) * 64, t);
            cp_commit();
            cp_wait1();
        } else {
            cp_wait0();
        }
        __syncthreads();
        const char* buf = sm + (ch & 1) * G2_BUF;
#pragma unroll
        for (int term = 0; term < 2; term++) {    // Ph@Vh, Ph@Vl
            const char* Pb = buf;
            const char* Vb = buf + 18432 + term * 9216;
#pragma unroll
            for (int ks = 0; ks < 4; ks++) {
                const int kb = ks * 32 + tg * 4;
                uint32_t a[2][4], b[4][2];
#pragma unroll
                for (int mt = 0; mt < 2; mt++) {
                    const char* p = Pb + (wm + mt * 16 + g) * 144 + kb;
                    a[mt][0] = *(const uint32_t*)p;
                    a[mt][1] = *(const uint32_t*)(p + 8 * 144);
                    a[mt][2] = *(const uint32_t*)(p + 16);
                    a[mt][3] = *(const uint32_t*)(p + 8 * 144 + 16);
                }
#pragma unroll
                for (int nt = 0; nt < 4; nt++) {
                    const char* p = Vb + (wn + nt * 8 + g) * 144 + kb;
                    b[nt][0] = *(const uint32_t*)p;
                    b[nt][1] = *(const uint32_t*)(p + 16);
                }
#pragma unroll
                for (int mt = 0; mt < 2; mt++)
#pragma unroll
                    for (int nt = 0; nt < 4; nt++)
                        mma_bf16(acc[mt][nt], a[mt], b[nt]);
            }
        }
        __syncthreads();
    }

    float* op = g_outpart + (size_t)blockIdx.y * NN * FF;
#pragma unroll
    for (int mt = 0; mt < 2; mt++)
#pragma unroll
        for (int nt = 0; nt < 4; nt++) {
            int r0 = i0 + wm + mt * 16 + g, c0 = wn + nt * 8 + tg * 2;
            *(float2*)(op + (size_t)r0 * FF + c0) =
                make_float2(acc[mt][nt][0], acc[mt][nt][1]);
            *(float2*)(op + (size_t)(r0 + 8) * FF + c0) =
                make_float2(acc[mt][nt][2], acc[mt][nt][3]);
        }
}

// ---------------- reduce 4 K-slices -------------------------------------------
__global__ void k_reduce_out(float* __restrict__ out) {
    int q = blockIdx.x * 256 + threadIdx.x;
    float4 s = ((const float4*)g_outpart)[q];
#pragma unroll
    for (int p = 1; p < 4; p++) {
        float4 v = ((const float4*)(g_outpart + (size_t)p * NN * FF))[q];
        s.x += v.x; s.y += v.y; s.z += v.z; s.w += v.w;
    }
    ((float4*)out)[q] = s;
}

// ---------------- stats + final -----------------------------------------------
__global__ void k_stats(const float* __restrict__ out) {
    __shared__ float sh[256];
    int b = blockIdx.x, t = threadIdx.x;
    const float4* row = (const float4*)(out + (size_t)(b * 256 + t) * FF);
    float ss = 0.f;
#pragma unroll
    for (int i = 0; i < 16; i++) {
        float4 v = row[i];
        ss += v.x * v.x + v.y * v.y + v.z * v.z + v.w * v.w;
    }
    sh[t] = ss;
    __syncthreads();
    for (int s = 128; s > 0; s >>= 1) {
        if (t < s) sh[t] += sh[t + s];
        __syncthreads();
    }
    if (t == 0) g_sumsq_part[b] = sh[0];
    __syncthreads();
    int f = t & 63, g = t >> 6;
    float cs = 0.f;
    for (int r = 0; r < 64; r++) cs += out[(size_t)(b * 256 + g * 64 + r) * FF + f];
    sh[t] = cs;
    __syncthreads();
    if (t < 64) g_colsum_part[b * FF + t] = sh[t] + sh[t + 64] + sh[t + 128] + sh[t + 192];
}

__global__ void k_final(float* __restrict__ out,
                        const float* __restrict__ wa1, const float* __restrict__ ba1,
                        const float* __restrict__ wa2, const float* __restrict__ ba2,
                        const float* __restrict__ wb1, const float* __restrict__ bb1,
                        const float* __restrict__ wb2, const float* __restrict__ bb2) {
    __shared__ float sh[64];
    int t = threadIdx.x;
    float cs = 0.f;
    for (int b = 0; b < 32; b++) cs += g_colsum_part[b * FF + t];
    sh[t] = cs * cs;
    __syncthreads();
    if (t == 0) {
        float s2 = 0.f;
        for (int i = 0; i < 64; i++) s2 += sh[i];
        float sq = 0.f;
        for (int b = 0; b < 32; b++) sq += g_sumsq_part[b];
        float m = 2.0f * sq / (float)NN - 2.0f * s2 / ((float)NN * (float)NN);
        float ha0 = tanhf(m * __ldg(wa1 + 0) + __ldg(ba1 + 0));
        float ha1 = tanhf(m * __ldg(wa1 + 1) + __ldg(ba1 + 1));
        float ao  = tanhf(ha0 * __ldg(wa2 + 0) + ha1 * __ldg(wa2 + 1) + __ldg(ba2));
        float hb0 = tanhf(m * __ldg(wb1 + 0) + __ldg(bb1 + 0));
        float hb1 = tanhf(m * __ldg(wb1 + 1) + __ldg(bb1 + 1));
        float bo  = tanhf(hb0 * __ldg(wb2 + 0) + hb1 * __ldg(wb2 + 1) + __ldg(bb2));
        out[NN * FF]     = expf(SLOPEC * ao);
        out[NN * FF + 1] = expf(-SLOPEC * bo);
    }
}

// ---------------- launch ------------------------------------------------------
extern "C" void kernel_launch(void* const* d_in, const int* in_sizes, int n_in,
                              void* d_out, int out_size) {
    const float* x     = (const float*)d_in[0];
    const float* w_in1 = (const float*)d_in[1];
    const float* b_in1 = (const float*)d_in[2];
    const float* w_in2 = (const float*)d_in[3];
    const float* b_in2 = (const float*)d_in[4];
    const float* w_in3 = (const float*)d_in[5];
    const float* b_in3 = (const float*)d_in[6];
    const float* w_a1  = (const float*)d_in[7];
    const float* b_a1  = (const float*)d_in[8];
    const float* w_a2  = (const float*)d_in[9];
    const float* b_a2  = (const float*)d_in[10];
    const float* w_b1  = (const float*)d_in[11];
    const float* b_b1  = (const float*)d_in[12];
    const float* w_b2  = (const float*)d_in[13];
    const float* b_b2  = (const float*)d_in[14];
    float* out = (float*)d_out;

    cudaFuncSetAttribute(k_gemm1, cudaFuncAttributeMaxDynamicSharedMemorySize, G1_SMEM);
    cudaFuncSetAttribute(k_gemm2, cudaFuncAttributeMaxDynamicSharedMemorySize, G2_SMEM);

    k_encode<<<NN * FF / 256, 256>>>(x, w_in1, b_in1, w_in2, b_in2, w_in3, b_in3);
    k_gemm1<<<dim3(64, 64), 256, G1_SMEM>>>();
    k_invd<<<32, 256>>>();
    k_prepV<<<NN / 64, 256>>>();
    k_gemm2<<<dim3(64, 4), 256, G2_SMEM>>>();
    k_reduce_out<<<NN * FF / 4 / 256, 256>>>(out);
    k_stats<<<32, 256>>>(out);
    k_final<<<1, 64>>>(out, w_a1, b_a1, w_a2, b_a2, w_b1, b_b1, w_b2, b_b2);
}